// round 1
// baseline (speedup 1.0000x reference)
#include <cuda_runtime.h>
#include <math.h>

#define NT 365
#define NS 2048
#define NH 64
#define NG 128
#define NW 513   // NH*8+1

// ---------------- scratch (static device globals; no allocation) -------------
__device__ float4 g_flux[(NT + 1) * NS];   // [t][s] = {Ps, Pl, E, Ta}; +1 row pad for prefetch
__device__ float  g_w[(size_t)NS * NW];    // raw fc output w[s][j]
__device__ float  g_par[11 * (size_t)NS * NH];
__device__ float  g_vi[NS];
__device__ float  g_qb[NS];

// param slots
#define P_GM   0
#define P_NGE  1
#define P_GL   2
#define P_NGL  3
#define P_K0M  4
#define P_K0GA 5
#define P_K1   6
#define P_KB   7
#define P_KQ1  8
#define P_K2M  9
#define P_K2GA 10

__device__ __forceinline__ float sigmoidf_(float x) {
    return 1.0f / (1.0f + expf(-x));
}

// ---------------- kernel A: rain/snow partition ------------------------------
__global__ void k_part(const float4* __restrict__ x) {
    int i = blockIdx.x * blockDim.x + threadIdx.x;
    if (i >= NT * NS) return;
    float4 v = x[i];
    float P = v.x, E = v.y, T1 = v.z, T2 = v.w;
    float Ta = 0.5f * (T1 + T2);
    float rP;
    if (T1 >= 0.0f)      rP = 1.0f;
    else if (T2 <= 0.0f) rP = 0.0f;
    else                 rP = 1.0f - acosf((T1 + T2) / (T2 - T1)) / 3.1415f;
    g_flux[i] = make_float4((1.0f - rP) * P, rP * P, E, Ta);
}

// ---------------- kernel B: w = xc @ W^T + b ---------------------------------
// grid (NS/32, 8), block 256. lane = site (xc varies per lane, W broadcast).
// Covers j in [0,512); j=512 handled in k_params.
__global__ void __launch_bounds__(256) k_gemm(const float* __restrict__ xc,
                                              const float4* __restrict__ W4,
                                              const float* __restrict__ b) {
    __shared__ float xs[32 * 132];  // 32 sites x 128, pad 132 (conflict-free, 16B aligned)
    int tid = threadIdx.x;
    int s0 = blockIdx.x << 5;
    int jbase = blockIdx.y << 6;

    for (int idx = tid; idx < 32 * NG; idx += 256) {
        int sl = idx >> 7, c = idx & (NG - 1);
        xs[sl * 132 + c] = xc[(size_t)(s0 + sl) * NG + c];
    }
    __syncthreads();

    int sl = tid & 31;      // site within tile
    int joff = tid >> 5;    // 0..7
    float acc[8] = {0.f, 0.f, 0.f, 0.f, 0.f, 0.f, 0.f, 0.f};
    const float4* wrow[8];
#pragma unroll
    for (int i = 0; i < 8; i++)
        wrow[i] = W4 + (size_t)(jbase + joff + i * 8) * (NG / 4);
    const float4* xv4 = (const float4*)&xs[sl * 132];

#pragma unroll 4
    for (int c4 = 0; c4 < NG / 4; ++c4) {
        float4 xv = xv4[c4];
#pragma unroll
        for (int i = 0; i < 8; i++) {
            float4 wv = wrow[i][c4];
            acc[i] += xv.x * wv.x + xv.y * wv.y + xv.z * wv.z + xv.w * wv.w;
        }
    }
#pragma unroll
    for (int i = 0; i < 8; i++) {
        int j = jbase + joff + i * 8;
        g_w[(size_t)(s0 + sl) * NW + j] = acc[i] + b[j];
    }
}

// ---------------- kernel C: activations + folded params ----------------------
// one warp per site; lane handles h = lane and h = lane+32
__global__ void __launch_bounds__(64) k_params(const float* __restrict__ xc,
                                               const float* __restrict__ W,
                                               const float* __restrict__ b) {
    int wid = (blockIdx.x * blockDim.x + threadIdx.x) >> 5;
    int lane = threadIdx.x & 31;
    if (wid >= NS) return;
    int s = wid;
    const float* wr = g_w + (size_t)s * NW;

    // cooperative dot for w[s][512]
    float p = 0.f;
    const float* w512row = W + 512 * NG;
    const float* xcr = xc + (size_t)s * NG;
#pragma unroll
    for (int k = 0; k < 4; k++)
        p = fmaf(xcr[lane + 32 * k], w512row[lane + 32 * k], p);
#pragma unroll
    for (int o = 16; o; o >>= 1) p += __shfl_xor_sync(0xffffffffu, p, o);
    float w512 = p + b[512];
    float vi = sigmoidf_(w512);
    float qb = fmaxf(w512, 0.f) / (float)NH;
    if (lane == 0) { g_vi[s] = vi; g_qb[s] = qb; }

    int hA = lane, hB = lane + 32;
    float wgmA = wr[0 * NH + hA], wgmB = wr[0 * NH + hB];
    float wgeA = wr[1 * NH + hA], wgeB = wr[1 * NH + hB];
    float wk0A = wr[3 * NH + hA], wk0B = wr[3 * NH + hB];
    float wk1A = wr[4 * NH + hA], wk1B = wr[4 * NH + hB];
    float wk2A = wr[5 * NH + hA], wk2B = wr[5 * NH + hB];
    float wglA = wr[6 * NH + hA], wglB = wr[6 * NH + hB];
    float wkbA = wr[7 * NH + hA], wkbB = wr[7 * NH + hB];

    // softmax over the k1 pre-activation slice (64 values across the warp)
    float m = fmaxf(wk1A, wk1B);
#pragma unroll
    for (int o = 16; o; o >>= 1) m = fmaxf(m, __shfl_xor_sync(0xffffffffu, m, o));
    float eA = expf(wk1A - m), eB = expf(wk1B - m);
    float sum = eA + eB;
#pragma unroll
    for (int o = 16; o; o >>= 1) sum += __shfl_xor_sync(0xffffffffu, sum, o);
    float inv = 1.0f / sum;
    float gaA = eA * inv, gaB = eB * inv;

    float gmA = expf(wgmA) + 1.0f,        gmB = expf(wgmB) + 1.0f;
    float geA = 2.0f * sigmoidf_(wgeA),   geB = 2.0f * sigmoidf_(wgeB);
    float glA = expf(wglA),               glB = expf(wglB);
    float k0A = sigmoidf_(wk0A),          k0B = sigmoidf_(wk0B);
    float k1A = sigmoidf_(wk1A),          k1B = sigmoidf_(wk1B);
    float k2A = sigmoidf_(wk2A),          k2B = sigmoidf_(wk2B);
    float kbA = sigmoidf_(wkbA) / 10.0f,  kbB = sigmoidf_(wkbB) / 10.0f;

    const size_t SP = (size_t)NS * NH;
    size_t bA = (size_t)s * NH + hA, bB = (size_t)s * NH + hB;
#define ST(pidx, vA, vB) { g_par[(pidx) * SP + bA] = (vA); g_par[(pidx) * SP + bB] = (vB); }
    ST(P_GM,   gmA,                 gmB);
    ST(P_NGE,  -geA,                -geB);
    ST(P_GL,   glA,                 glB);
    ST(P_NGL,  -glA,                -glB);
    ST(P_K0M,  1.0f - k0A,          1.0f - k0B);
    ST(P_K0GA, k0A * gaA,           k0B * gaB);
    ST(P_K1,   k1A,                 k1B);
    ST(P_KB,   kbA,                 kbB);
    ST(P_KQ1,  k1A * (1.0f - kbA) * gaA, k1B * (1.0f - kbB) * gaB);
    ST(P_K2M,  1.0f - k2A,          1.0f - k2B);
    ST(P_K2GA, k2A * gaA,           k2B * gaB);
#undef ST
}

// ---------------- kernel D: sequential scan ----------------------------------
// one warp per site; lane carries state for h=lane and h=lane+32
__global__ void __launch_bounds__(64) k_scan(float* __restrict__ out) {
    int wid = (blockIdx.x * blockDim.x + threadIdx.x) >> 5;
    int lane = threadIdx.x & 31;
    int s = wid;
    const size_t SP = (size_t)NS * NH;
    size_t base = (size_t)s * NH + lane;

#define LD2(p, a, b) float a = g_par[(p) * SP + base]; float b = g_par[(p) * SP + base + 32];
    LD2(P_GM,   gmA,   gmB)
    LD2(P_NGE,  ngeA,  ngeB)
    LD2(P_GL,   glA,   glB)
    LD2(P_NGL,  nglA,  nglB)
    LD2(P_K0M,  k0mA,  k0mB)
    LD2(P_K0GA, k0gaA, k0gaB)
    LD2(P_K1,   k1A,   k1B)
    LD2(P_KB,   kbA,   kbB)
    LD2(P_KQ1,  kq1A,  kq1B)
    LD2(P_K2M,  k2mA,  k2mB)
    LD2(P_K2GA, k2gaA, k2gaB)
#undef LD2
    float vi = g_vi[s];
    float qb = g_qb[s];

    // state (H0 carried shifted: H0s = H0 - gl, init H0=0 -> H0s = -gl)
    float S0A = 0.f, S0B = 0.f;
    float H0A = nglA, H0B = nglB;
    float H1A = 0.f, H1B = 0.f;
    float H2A = 0.f, H2B = 0.f;

    float4 f = g_flux[s];  // t = 0
    for (int t = 0; t < NT; ++t) {
        float4 fn = g_flux[(size_t)(t + 1) * NS + s];  // padded row at t=NT-1
        float ps = f.x, pl = f.y, e = f.z, ta = f.w;
        float plvi = pl * vi;
        float plv1 = pl - plvi;

        // ---- half A ----
        float amA = fmaxf(ta * gmA, 0.f);
        float SmA = fminf(S0A, amA);
        S0A = S0A + (ps - SmA);
        float c1A = fmaf(e, ngeA, plvi);
        float G1A = fmaxf(H1A + SmA + c1A, 0.f);
        float G0A = fmaxf(H0A + G1A + plv1, 0.f);
        H0A = fmaf(G0A, k0mA, nglA);
        float y = G0A * k0gaA;
        float m1A = fminf(G1A, glA);
        float Q1A = m1A * k1A;
        H1A = fminf(G1A - Q1A, glA);
        float G2A = fmaf(Q1A, kbA, H2A);
        H2A = G2A * k2mA;
        y = fmaf(G2A, k2gaA, y);
        y = fmaf(m1A, kq1A, y);

        // ---- half B ----
        float amB = fmaxf(ta * gmB, 0.f);
        float SmB = fminf(S0B, amB);
        S0B = S0B + (ps - SmB);
        float c1B = fmaf(e, ngeB, plvi);
        float G1B = fmaxf(H1B + SmB + c1B, 0.f);
        float G0B = fmaxf(H0B + G1B + plv1, 0.f);
        H0B = fmaf(G0B, k0mB, nglB);
        y = fmaf(G0B, k0gaB, y);
        float m1B = fminf(G1B, glB);
        float Q1B = m1B * k1B;
        H1B = fminf(G1B - Q1B, glB);
        float G2B = fmaf(Q1B, kbB, H2B);
        H2B = G2B * k2mB;
        y = fmaf(G2B, k2gaB, y);
        y = fmaf(m1B, kq1B, y);

        // ---- reduce 64 h across warp ----
#pragma unroll
        for (int o = 16; o; o >>= 1) y += __shfl_xor_sync(0xffffffffu, y, o);
        if (lane == 0) out[(size_t)t * NS + s] = y + qb;  // qb * sum(ga) == qb
        f = fn;
    }
}

// ---------------- launch ------------------------------------------------------
extern "C" void kernel_launch(void* const* d_in, const int* in_sizes, int n_in,
                              void* d_out, int out_size) {
    const float* x  = (const float*)d_in[0];  // [NT, NS, 4]
    const float* xc = (const float*)d_in[1];  // [NS, NG]
    const float* W  = (const float*)d_in[2];  // [NW, NG]
    const float* b  = (const float*)d_in[3];  // [NW]
    float* out = (float*)d_out;               // [NT, NS]

    k_part<<<(NT * NS + 255) / 256, 256>>>((const float4*)x);

    dim3 gB(NS / 32, 8);
    k_gemm<<<gB, 256>>>(xc, (const float4*)W, b);

    k_params<<<NS / 2, 64>>>(xc, W, b);   // 2 warps/block, 1 site per warp
    k_scan<<<NS / 2, 64>>>(out);
}

// round 2
// speedup vs baseline: 1.6311x; 1.6311x over previous
#include <cuda_runtime.h>
#include <math.h>

#define NT 365
#define NS 2048
#define NH 64
#define NG 128
#define NW 513   // NH*8+1

// ---------------- scratch (static device globals; no allocation) -------------
__device__ float4 g_flux[(NT + 4) * NS];   // [t][s]; +4 rows (zero) for prefetch overrun
__device__ float  g_w[(size_t)NS * NW];    // raw fc output w[s][j]
__device__ float  g_par[11 * (size_t)NS * NH];
__device__ float  g_vi[NS];
__device__ float  g_qb[NS];

// param slots (folded)
#define P_GM   0   // exp(w)+1
#define P_NGE  1   // -2*sigmoid(w_ge)
#define P_GL   2   // exp(w_gl)
#define P_NGL  3   // -gl
#define P_K0M  4   // 1-k0
#define P_K0GA 5   // k0*ga
#define P_NK1  6   // -k1
#define P_KKB  7   // k1*kb
#define P_KQ1  8   // k1*(1-kb)*ga
#define P_K2M  9   // 1-k2
#define P_K2GA 10  // k2*ga

__device__ __forceinline__ float sigmoidf_(float x) {
    return 1.0f / (1.0f + expf(-x));
}

// ---------------- kernel A: rain/snow partition ------------------------------
__global__ void k_part(const float4* __restrict__ x) {
    int i = blockIdx.x * blockDim.x + threadIdx.x;
    if (i >= NT * NS) return;
    float4 v = x[i];
    float P = v.x, E = v.y, T1 = v.z, T2 = v.w;
    float Ta = 0.5f * (T1 + T2);
    float rP;
    if (T1 >= 0.0f)      rP = 1.0f;
    else if (T2 <= 0.0f) rP = 0.0f;
    else                 rP = 1.0f - acosf((T1 + T2) / (T2 - T1)) / 3.1415f;
    g_flux[i] = make_float4((1.0f - rP) * P, rP * P, E, Ta);
}

// ---------------- kernel B: w = xc @ W^T + b ---------------------------------
__global__ void __launch_bounds__(256) k_gemm(const float* __restrict__ xc,
                                              const float4* __restrict__ W4,
                                              const float* __restrict__ b) {
    __shared__ float xs[32 * 132];
    int tid = threadIdx.x;
    int s0 = blockIdx.x << 5;
    int jbase = blockIdx.y << 6;

    for (int idx = tid; idx < 32 * NG; idx += 256) {
        int sl = idx >> 7, c = idx & (NG - 1);
        xs[sl * 132 + c] = xc[(size_t)(s0 + sl) * NG + c];
    }
    __syncthreads();

    int sl = tid & 31;
    int joff = tid >> 5;
    float acc[8] = {0.f, 0.f, 0.f, 0.f, 0.f, 0.f, 0.f, 0.f};
    const float4* wrow[8];
#pragma unroll
    for (int i = 0; i < 8; i++)
        wrow[i] = W4 + (size_t)(jbase + joff + i * 8) * (NG / 4);
    const float4* xv4 = (const float4*)&xs[sl * 132];

#pragma unroll 4
    for (int c4 = 0; c4 < NG / 4; ++c4) {
        float4 xv = xv4[c4];
#pragma unroll
        for (int i = 0; i < 8; i++) {
            float4 wv = wrow[i][c4];
            acc[i] += xv.x * wv.x + xv.y * wv.y + xv.z * wv.z + xv.w * wv.w;
        }
    }
#pragma unroll
    for (int i = 0; i < 8; i++) {
        int j = jbase + joff + i * 8;
        g_w[(size_t)(s0 + sl) * NW + j] = acc[i] + b[j];
    }
}

// ---------------- kernel C: activations + folded params ----------------------
__global__ void __launch_bounds__(64) k_params(const float* __restrict__ xc,
                                               const float* __restrict__ W,
                                               const float* __restrict__ b) {
    int wid = (blockIdx.x * blockDim.x + threadIdx.x) >> 5;
    int lane = threadIdx.x & 31;
    if (wid >= NS) return;
    int s = wid;
    const float* wr = g_w + (size_t)s * NW;

    // cooperative dot for w[s][512]
    float p = 0.f;
    const float* w512row = W + 512 * NG;
    const float* xcr = xc + (size_t)s * NG;
#pragma unroll
    for (int k = 0; k < 4; k++)
        p = fmaf(xcr[lane + 32 * k], w512row[lane + 32 * k], p);
#pragma unroll
    for (int o = 16; o; o >>= 1) p += __shfl_xor_sync(0xffffffffu, p, o);
    float w512 = p + b[512];
    float vi = sigmoidf_(w512);
    float qb = fmaxf(w512, 0.f) / (float)NH;
    if (lane == 0) { g_vi[s] = vi; g_qb[s] = qb; }

    int hA = lane, hB = lane + 32;
    float wgmA = wr[0 * NH + hA], wgmB = wr[0 * NH + hB];
    float wgeA = wr[1 * NH + hA], wgeB = wr[1 * NH + hB];
    float wk0A = wr[3 * NH + hA], wk0B = wr[3 * NH + hB];
    float wk1A = wr[4 * NH + hA], wk1B = wr[4 * NH + hB];
    float wk2A = wr[5 * NH + hA], wk2B = wr[5 * NH + hB];
    float wglA = wr[6 * NH + hA], wglB = wr[6 * NH + hB];
    float wkbA = wr[7 * NH + hA], wkbB = wr[7 * NH + hB];

    // softmax over the k1 pre-activation slice (64 values across the warp)
    float m = fmaxf(wk1A, wk1B);
#pragma unroll
    for (int o = 16; o; o >>= 1) m = fmaxf(m, __shfl_xor_sync(0xffffffffu, m, o));
    float eA = expf(wk1A - m), eB = expf(wk1B - m);
    float sum = eA + eB;
#pragma unroll
    for (int o = 16; o; o >>= 1) sum += __shfl_xor_sync(0xffffffffu, sum, o);
    float inv = 1.0f / sum;
    float gaA = eA * inv, gaB = eB * inv;

    float gmA = expf(wgmA) + 1.0f,        gmB = expf(wgmB) + 1.0f;
    float geA = 2.0f * sigmoidf_(wgeA),   geB = 2.0f * sigmoidf_(wgeB);
    float glA = expf(wglA),               glB = expf(wglB);
    float k0A = sigmoidf_(wk0A),          k0B = sigmoidf_(wk0B);
    float k1A = sigmoidf_(wk1A),          k1B = sigmoidf_(wk1B);
    float k2A = sigmoidf_(wk2A),          k2B = sigmoidf_(wk2B);
    float kbA = sigmoidf_(wkbA) / 10.0f,  kbB = sigmoidf_(wkbB) / 10.0f;

    const size_t SP = (size_t)NS * NH;
    size_t bA = (size_t)s * NH + hA, bB = (size_t)s * NH + hB;
#define ST(pidx, vA, vB) { g_par[(pidx) * SP + bA] = (vA); g_par[(pidx) * SP + bB] = (vB); }
    ST(P_GM,   gmA,                 gmB);
    ST(P_NGE,  -geA,                -geB);
    ST(P_GL,   glA,                 glB);
    ST(P_NGL,  -glA,                -glB);
    ST(P_K0M,  1.0f - k0A,          1.0f - k0B);
    ST(P_K0GA, k0A * gaA,           k0B * gaB);
    ST(P_NK1,  -k1A,                -k1B);
    ST(P_KKB,  k1A * kbA,           k1B * kbB);
    ST(P_KQ1,  k1A * (1.0f - kbA) * gaA, k1B * (1.0f - kbB) * gaB);
    ST(P_K2M,  1.0f - k2A,          1.0f - k2B);
    ST(P_K2GA, k2A * gaA,           k2B * gaB);
#undef ST
}

// ---------------- kernel D: sequential scan ----------------------------------
// one warp handles 2 sites; 16 lanes per site; each lane carries 4 h
// (h = l, l+16, l+32, l+48 where l = lane & 15)
__global__ void __launch_bounds__(32) k_scan(float* __restrict__ out) {
    int warp = blockIdx.x;               // 0..1023, one warp per block
    int lane = threadIdx.x;              // 0..31
    int half = lane >> 4;                // 0 / 1 -> site select
    int l    = lane & 15;
    int s    = warp * 2 + half;

    const size_t SP = (size_t)NS * NH;
    size_t base = (size_t)s * NH + l;    // + {0,16,32,48}

    float gm[4], nge[4], gl[4], ngl[4], k0m[4], k0ga[4], nk1[4], kkb[4],
          kq1[4], k2m[4], k2ga[4];
#pragma unroll
    for (int j = 0; j < 4; ++j) {
        size_t o = base + 16 * j;
        gm[j]   = g_par[P_GM   * SP + o];
        nge[j]  = g_par[P_NGE  * SP + o];
        gl[j]   = g_par[P_GL   * SP + o];
        ngl[j]  = g_par[P_NGL  * SP + o];
        k0m[j]  = g_par[P_K0M  * SP + o];
        k0ga[j] = g_par[P_K0GA * SP + o];
        nk1[j]  = g_par[P_NK1  * SP + o];
        kkb[j]  = g_par[P_KKB  * SP + o];
        kq1[j]  = g_par[P_KQ1  * SP + o];
        k2m[j]  = g_par[P_K2M  * SP + o];
        k2ga[j] = g_par[P_K2GA * SP + o];
    }
    float vi = g_vi[s];
    float qb = g_qb[s];

    float S0[4], H0[4], H1[4], H2[4];
#pragma unroll
    for (int j = 0; j < 4; ++j) { S0[j] = 0.f; H0[j] = ngl[j]; H1[j] = 0.f; H2[j] = 0.f; }

    // one step of the recurrence for this lane's 4 h, plus reduce + store
#define STEP(F, T)                                                             \
    {                                                                          \
        float ps = F.x, pl = F.y, e = F.z, ta = F.w;                           \
        float plvi = pl * vi;                                                  \
        float plv1 = pl - plvi;                                                \
        float tap  = fmaxf(ta, 0.f);                                           \
        float y0 = 0.f, y1 = 0.f;                                              \
        _Pragma("unroll")                                                      \
        for (int j = 0; j < 4; ++j) {                                          \
            float am = tap * gm[j];                                            \
            float Sm = fminf(S0[j], am);                                       \
            S0[j] += (ps - Sm);                                                \
            float G1 = fmaxf(H1[j] + Sm + fmaf(e, nge[j], plvi), 0.f);         \
            float G0 = fmaxf(H0[j] + G1 + plv1, 0.f);                          \
            H0[j] = fmaf(G0, k0m[j], ngl[j]);                                  \
            y0 = fmaf(G0, k0ga[j], y0);                                        \
            float m1 = fminf(G1, gl[j]);                                       \
            H1[j] = fminf(fmaf(m1, nk1[j], G1), gl[j]);                        \
            float G2 = fmaf(m1, kkb[j], H2[j]);                                \
            H2[j] = G2 * k2m[j];                                               \
            y1 = fmaf(G2, k2ga[j], y1);                                        \
            y1 = fmaf(m1, kq1[j], y1);                                         \
        }                                                                      \
        float y = y0 + y1;                                                     \
        _Pragma("unroll")                                                      \
        for (int o = 8; o; o >>= 1) y += __shfl_xor_sync(0xffffffffu, y, o);   \
        if (l == 0) out[(size_t)(T) * NS + s] = y + qb;                        \
    }

    // preload flux block 0 (steps 0..3)
    float4 fc0 = g_flux[0 * NS + s];
    float4 fc1 = g_flux[1 * NS + s];
    float4 fc2 = g_flux[2 * NS + s];
    float4 fc3 = g_flux[3 * NS + s];

    for (int tb = 0; tb < 91; ++tb) {
        int t = tb * 4;
        // prefetch next block (rows t+4 .. t+7; padded to NT+4 so max 367 is safe)
        float4 fn0 = g_flux[(size_t)(t + 4) * NS + s];
        float4 fn1 = g_flux[(size_t)(t + 5) * NS + s];
        float4 fn2 = g_flux[(size_t)(t + 6) * NS + s];
        float4 fn3 = g_flux[(size_t)(t + 7) * NS + s];

        STEP(fc0, t + 0)
        STEP(fc1, t + 1)
        STEP(fc2, t + 2)
        STEP(fc3, t + 3)

        fc0 = fn0; fc1 = fn1; fc2 = fn2; fc3 = fn3;
    }
    // epilogue: t = 364
    STEP(fc0, 364)
#undef STEP
}

// ---------------- launch ------------------------------------------------------
extern "C" void kernel_launch(void* const* d_in, const int* in_sizes, int n_in,
                              void* d_out, int out_size) {
    const float* x  = (const float*)d_in[0];  // [NT, NS, 4]
    const float* xc = (const float*)d_in[1];  // [NS, NG]
    const float* W  = (const float*)d_in[2];  // [NW, NG]
    const float* b  = (const float*)d_in[3];  // [NW]
    float* out = (float*)d_out;               // [NT, NS]

    k_part<<<(NT * NS + 255) / 256, 256>>>((const float4*)x);

    dim3 gB(NS / 32, 8);
    k_gemm<<<gB, 256>>>(xc, (const float4*)W, b);

    k_params<<<NS / 2, 64>>>(xc, W, b);
    k_scan<<<NS / 2, 32>>>(out);   // 1024 blocks, 1 warp each, 2 sites/warp
}

// round 3
// speedup vs baseline: 1.6954x; 1.0394x over previous
#include <cuda_runtime.h>
#include <math.h>

#define NT 365
#define NS 2048
#define NH 64
#define NG 128
#define NW 513   // NH*8+1

// ---------------- scratch (static device globals; no allocation) -------------
__device__ float4 g_flux[(NT + 4) * NS];   // [t][s] = {ps, pl*vi, pl*(1-vi), e}
__device__ float  g_tap[(NT + 4) * NS];    // [t][s] = relu(Ta)
__device__ float  g_w[(size_t)NS * NW];    // raw fc output w[s][j]
__device__ float  g_par[11 * (size_t)NS * NH];
__device__ float  g_vi[NS];
__device__ float  g_qb[NS];

// param slots (folded)
#define P_GM   0   // exp(w)+1
#define P_NGE  1   // -2*sigmoid(w_ge)
#define P_GL   2   // exp(w_gl)
#define P_NGL  3   // -gl
#define P_K0M  4   // 1-k0
#define P_K0GA 5   // k0*ga
#define P_NK1  6   // -k1
#define P_KKB  7   // k1*kb
#define P_KQ1  8   // k1*(1-kb)*ga
#define P_K2M  9   // 1-k2
#define P_K2GA 10  // k2*ga

__device__ __forceinline__ float sigmoidf_(float x) {
    return 1.0f / (1.0f + expf(-x));
}

// ---------------- kernel A: rain/snow partition + per-site folds -------------
// runs AFTER k_params (needs g_vi)
__global__ void k_part(const float4* __restrict__ x) {
    int i = blockIdx.x * blockDim.x + threadIdx.x;
    if (i >= NT * NS) return;
    int s = i & (NS - 1);
    float4 v = x[i];
    float P = v.x, E = v.y, T1 = v.z, T2 = v.w;
    float Ta = 0.5f * (T1 + T2);
    float rP;
    if (T1 >= 0.0f)      rP = 1.0f;
    else if (T2 <= 0.0f) rP = 0.0f;
    else                 rP = 1.0f - acosf((T1 + T2) / (T2 - T1)) / 3.1415f;
    float pl = rP * P;
    float ps = (1.0f - rP) * P;
    float vi = g_vi[s];
    float plvi = pl * vi;
    g_flux[i] = make_float4(ps, plvi, pl - plvi, E);
    g_tap[i] = fmaxf(Ta, 0.0f);
}

// ---------------- kernel B: w = xc @ W^T + b ---------------------------------
__global__ void __launch_bounds__(256) k_gemm(const float* __restrict__ xc,
                                              const float4* __restrict__ W4,
                                              const float* __restrict__ b) {
    __shared__ float xs[32 * 132];
    int tid = threadIdx.x;
    int s0 = blockIdx.x << 5;
    int jbase = blockIdx.y << 6;

    for (int idx = tid; idx < 32 * NG; idx += 256) {
        int sl = idx >> 7, c = idx & (NG - 1);
        xs[sl * 132 + c] = xc[(size_t)(s0 + sl) * NG + c];
    }
    __syncthreads();

    int sl = tid & 31;
    int joff = tid >> 5;
    float acc[8] = {0.f, 0.f, 0.f, 0.f, 0.f, 0.f, 0.f, 0.f};
    const float4* wrow[8];
#pragma unroll
    for (int i = 0; i < 8; i++)
        wrow[i] = W4 + (size_t)(jbase + joff + i * 8) * (NG / 4);
    const float4* xv4 = (const float4*)&xs[sl * 132];

#pragma unroll 4
    for (int c4 = 0; c4 < NG / 4; ++c4) {
        float4 xv = xv4[c4];
#pragma unroll
        for (int i = 0; i < 8; i++) {
            float4 wv = wrow[i][c4];
            acc[i] += xv.x * wv.x + xv.y * wv.y + xv.z * wv.z + xv.w * wv.w;
        }
    }
#pragma unroll
    for (int i = 0; i < 8; i++) {
        int j = jbase + joff + i * 8;
        g_w[(size_t)(s0 + sl) * NW + j] = acc[i] + b[j];
    }
}

// ---------------- kernel C: activations + folded params ----------------------
__global__ void __launch_bounds__(64) k_params(const float* __restrict__ xc,
                                               const float* __restrict__ W,
                                               const float* __restrict__ b) {
    int wid = (blockIdx.x * blockDim.x + threadIdx.x) >> 5;
    int lane = threadIdx.x & 31;
    if (wid >= NS) return;
    int s = wid;
    const float* wr = g_w + (size_t)s * NW;

    // cooperative dot for w[s][512]
    float p = 0.f;
    const float* w512row = W + 512 * NG;
    const float* xcr = xc + (size_t)s * NG;
#pragma unroll
    for (int k = 0; k < 4; k++)
        p = fmaf(xcr[lane + 32 * k], w512row[lane + 32 * k], p);
#pragma unroll
    for (int o = 16; o; o >>= 1) p += __shfl_xor_sync(0xffffffffu, p, o);
    float w512 = p + b[512];
    float vi = sigmoidf_(w512);
    float qb = fmaxf(w512, 0.f) / (float)NH;
    if (lane == 0) { g_vi[s] = vi; g_qb[s] = qb; }

    int hA = lane, hB = lane + 32;
    float wgmA = wr[0 * NH + hA], wgmB = wr[0 * NH + hB];
    float wgeA = wr[1 * NH + hA], wgeB = wr[1 * NH + hB];
    float wk0A = wr[3 * NH + hA], wk0B = wr[3 * NH + hB];
    float wk1A = wr[4 * NH + hA], wk1B = wr[4 * NH + hB];
    float wk2A = wr[5 * NH + hA], wk2B = wr[5 * NH + hB];
    float wglA = wr[6 * NH + hA], wglB = wr[6 * NH + hB];
    float wkbA = wr[7 * NH + hA], wkbB = wr[7 * NH + hB];

    // softmax over the k1 pre-activation slice (64 values across the warp)
    float m = fmaxf(wk1A, wk1B);
#pragma unroll
    for (int o = 16; o; o >>= 1) m = fmaxf(m, __shfl_xor_sync(0xffffffffu, m, o));
    float eA = expf(wk1A - m), eB = expf(wk1B - m);
    float sum = eA + eB;
#pragma unroll
    for (int o = 16; o; o >>= 1) sum += __shfl_xor_sync(0xffffffffu, sum, o);
    float inv = 1.0f / sum;
    float gaA = eA * inv, gaB = eB * inv;

    float gmA = expf(wgmA) + 1.0f,        gmB = expf(wgmB) + 1.0f;
    float geA = 2.0f * sigmoidf_(wgeA),   geB = 2.0f * sigmoidf_(wgeB);
    float glA = expf(wglA),               glB = expf(wglB);
    float k0A = sigmoidf_(wk0A),          k0B = sigmoidf_(wk0B);
    float k1A = sigmoidf_(wk1A),          k1B = sigmoidf_(wk1B);
    float k2A = sigmoidf_(wk2A),          k2B = sigmoidf_(wk2B);
    float kbA = sigmoidf_(wkbA) / 10.0f,  kbB = sigmoidf_(wkbB) / 10.0f;

    const size_t SP = (size_t)NS * NH;
    size_t bA = (size_t)s * NH + hA, bB = (size_t)s * NH + hB;
#define ST(pidx, vA, vB) { g_par[(pidx) * SP + bA] = (vA); g_par[(pidx) * SP + bB] = (vB); }
    ST(P_GM,   gmA,                 gmB);
    ST(P_NGE,  -geA,                -geB);
    ST(P_GL,   glA,                 glB);
    ST(P_NGL,  -glA,                -glB);
    ST(P_K0M,  1.0f - k0A,          1.0f - k0B);
    ST(P_K0GA, k0A * gaA,           k0B * gaB);
    ST(P_NK1,  -k1A,                -k1B);
    ST(P_KKB,  k1A * kbA,           k1B * kbB);
    ST(P_KQ1,  k1A * (1.0f - kbA) * gaA, k1B * (1.0f - kbB) * gaB);
    ST(P_K2M,  1.0f - k2A,          1.0f - k2B);
    ST(P_K2GA, k2A * gaA,           k2B * gaB);
#undef ST
}

// ---------------- kernel D: sequential scan ----------------------------------
// one warp handles 2 sites; 16 lanes per site; each lane carries 4 h
// (h = l, l+16, l+32, l+48 where l = lane & 15)
// reduction + stores deferred/batched over 4 unrolled timesteps
__global__ void __launch_bounds__(32) k_scan(float* __restrict__ out) {
    int warp = blockIdx.x;               // 0..1023, one warp per block
    int lane = threadIdx.x;              // 0..31
    int l    = lane & 15;
    int s    = warp * 2 + (lane >> 4);

    const size_t SP = (size_t)NS * NH;
    size_t base = (size_t)s * NH + l;    // + {0,16,32,48}

    float gm[4], nge[4], gl[4], ngl[4], k0m[4], k0ga[4], nk1[4], kkb[4],
          kq1[4], k2m[4], k2ga[4];
#pragma unroll
    for (int j = 0; j < 4; ++j) {
        size_t o = base + 16 * j;
        gm[j]   = g_par[P_GM   * SP + o];
        nge[j]  = g_par[P_NGE  * SP + o];
        gl[j]   = g_par[P_GL   * SP + o];
        ngl[j]  = g_par[P_NGL  * SP + o];
        k0m[j]  = g_par[P_K0M  * SP + o];
        k0ga[j] = g_par[P_K0GA * SP + o];
        nk1[j]  = g_par[P_NK1  * SP + o];
        kkb[j]  = g_par[P_KKB  * SP + o];
        kq1[j]  = g_par[P_KQ1  * SP + o];
        k2m[j]  = g_par[P_K2M  * SP + o];
        k2ga[j] = g_par[P_K2GA * SP + o];
    }
    float qb = g_qb[s];

    float S0[4], H0[4], H1[4], H2[4], yv[4];
#pragma unroll
    for (int j = 0; j < 4; ++j) { S0[j] = 0.f; H0[j] = ngl[j]; H1[j] = 0.f; H2[j] = 0.f; }

    // one step of the recurrence for this lane's 4 h; y kept in yv[K]
#define STEP(F, TP, K)                                                         \
    {                                                                          \
        float ps = F.x, plvi = F.y, plv1 = F.z, e = F.w;                       \
        float tap = TP;                                                        \
        float y0 = 0.f, y1 = 0.f;                                              \
        _Pragma("unroll")                                                      \
        for (int j = 0; j < 4; ++j) {                                          \
            float am = tap * gm[j];                                            \
            float Sm = fminf(S0[j], am);                                       \
            S0[j] = (S0[j] - Sm) + ps;                                         \
            float G1 = fmaxf((H1[j] + Sm) + fmaf(e, nge[j], plvi), 0.f);       \
            float G0 = fmaxf((H0[j] + G1) + plv1, 0.f);                        \
            H0[j] = fmaf(G0, k0m[j], ngl[j]);                                  \
            y0 = fmaf(G0, k0ga[j], y0);                                        \
            float m1 = fminf(G1, gl[j]);                                       \
            H1[j] = fminf(fmaf(m1, nk1[j], G1), gl[j]);                        \
            float G2 = fmaf(m1, kkb[j], H2[j]);                                \
            H2[j] = G2 * k2m[j];                                               \
            y1 = fmaf(G2, k2ga[j], y1);                                        \
            y0 = fmaf(m1, kq1[j], y0);                                         \
        }                                                                      \
        yv[K] = y0 + y1;                                                       \
    }

    // interleaved 16-lane butterfly over the 4 deferred y values
#define REDUCE_STORE(T, NSTEPS)                                                \
    {                                                                          \
        _Pragma("unroll")                                                      \
        for (int o = 8; o; o >>= 1) {                                          \
            float u0 = __shfl_xor_sync(0xffffffffu, yv[0], o);                 \
            float u1 = __shfl_xor_sync(0xffffffffu, yv[1], o);                 \
            float u2 = __shfl_xor_sync(0xffffffffu, yv[2], o);                 \
            float u3 = __shfl_xor_sync(0xffffffffu, yv[3], o);                 \
            yv[0] += u0; yv[1] += u1; yv[2] += u2; yv[3] += u3;                \
        }                                                                      \
        if (l == 0) {                                                          \
            _Pragma("unroll")                                                  \
            for (int k = 0; k < (NSTEPS); ++k)                                 \
                out[(size_t)((T) + k) * NS + s] = yv[k] + qb;                  \
        }                                                                      \
    }

    // preload flux block 0 (steps 0..3)
    float4 fc0 = g_flux[0 * NS + s];
    float4 fc1 = g_flux[1 * NS + s];
    float4 fc2 = g_flux[2 * NS + s];
    float4 fc3 = g_flux[3 * NS + s];
    float  tp0 = g_tap[0 * NS + s];
    float  tp1 = g_tap[1 * NS + s];
    float  tp2 = g_tap[2 * NS + s];
    float  tp3 = g_tap[3 * NS + s];

    for (int tb = 0; tb < 91; ++tb) {
        int t = tb * 4;
        // prefetch next block (rows t+4 .. t+7; arrays padded to NT+4 rows)
        float4 fn0 = g_flux[(size_t)(t + 4) * NS + s];
        float4 fn1 = g_flux[(size_t)(t + 5) * NS + s];
        float4 fn2 = g_flux[(size_t)(t + 6) * NS + s];
        float4 fn3 = g_flux[(size_t)(t + 7) * NS + s];
        float  tn0 = g_tap[(size_t)(t + 4) * NS + s];
        float  tn1 = g_tap[(size_t)(t + 5) * NS + s];
        float  tn2 = g_tap[(size_t)(t + 6) * NS + s];
        float  tn3 = g_tap[(size_t)(t + 7) * NS + s];

        STEP(fc0, tp0, 0)
        STEP(fc1, tp1, 1)
        STEP(fc2, tp2, 2)
        STEP(fc3, tp3, 3)
        REDUCE_STORE(t, 4)

        fc0 = fn0; fc1 = fn1; fc2 = fn2; fc3 = fn3;
        tp0 = tn0; tp1 = tn1; tp2 = tn2; tp3 = tn3;
    }
    // epilogue: t = 364
    STEP(fc0, tp0, 0)
    REDUCE_STORE(364, 1)
#undef STEP
#undef REDUCE_STORE
}

// ---------------- launch ------------------------------------------------------
extern "C" void kernel_launch(void* const* d_in, const int* in_sizes, int n_in,
                              void* d_out, int out_size) {
    const float* x  = (const float*)d_in[0];  // [NT, NS, 4]
    const float* xc = (const float*)d_in[1];  // [NS, NG]
    const float* W  = (const float*)d_in[2];  // [NW, NG]
    const float* b  = (const float*)d_in[3];  // [NW]
    float* out = (float*)d_out;               // [NT, NS]

    dim3 gB(NS / 32, 8);
    k_gemm<<<gB, 256>>>(xc, (const float4*)W, b);
    k_params<<<NS / 2, 64>>>(xc, W, b);
    k_part<<<(NT * NS + 255) / 256, 256>>>((const float4*)x);  // needs g_vi
    k_scan<<<NS / 2, 32>>>(out);   // 1024 blocks, 1 warp each, 2 sites/warp
}